// round 1
// baseline (speedup 1.0000x reference)
#include <cuda_runtime.h>

// Problem constants
constexpr int BB  = 8;
constexpr int CC  = 512;
constexpr int LL  = 64;
constexpr int NHW = 4096;
constexpr int PPc = 256;

// gain = 1/sqrt(512) for [64,512] convs; 1/sqrt(64)=0.125 for w_o
#define GAIN_IN 0.04419417382415922f
#define GAIN_O  0.125f

// -------- device scratch (static, allowed) --------
__device__ float g_th [BB * LL * NHW];
__device__ float g_ph [BB * LL * NHW];
__device__ float g_gv [BB * LL * NHW];
__device__ float g_lat[BB * NHW * LL];    // written [b][n][c]; read as [b][l][hw]
__device__ float g_sa [BB * CC * NHW];
__device__ float g_enc[BB * LL * NHW];
__device__ float g_lat2[BB * NHW * LL];

// ============================================================
// proj: out[b][o][n] = gain * sum_c W[o][c] * X[b][c][n]
// O = 64 (full), N tile = 128, K(c) chunked by 32.
// grid (32 ntiles, 8 b), 256 threads.
// ============================================================
__global__ __launch_bounds__(256) void proj_kernel(
    const float* __restrict__ X, const float* __restrict__ W,
    float* __restrict__ out, float gain)
{
    __shared__ float Ws[32][68];    // [c_local][o]
    __shared__ float Xs[32][132];   // [c_local][n_local]

    const int tid = threadIdx.x;
    const int b  = blockIdx.y;
    const int n0 = blockIdx.x * 128;
    const int ty = tid >> 4;        // 0..15 -> o group (4 each)
    const int tx = tid & 15;        // 0..15 -> n group (8 each)

    const float* Xb = X + (size_t)b * CC * NHW;

    float acc[4][8];
#pragma unroll
    for (int i = 0; i < 4; i++)
#pragma unroll
        for (int j = 0; j < 8; j++) acc[i][j] = 0.f;

    for (int c0 = 0; c0 < CC; c0 += 32) {
        __syncthreads();
        // load W chunk transposed: Ws[cl][o] = W[o][c0+cl]
        {
            const int o  = tid >> 3;          // 0..31
            const int c4 = (tid & 7) << 2;    // 0,4,..28
#pragma unroll
            for (int p2 = 0; p2 < 2; p2++) {
                const int oo = o + p2 * 32;
                float4 w = *(const float4*)&W[oo * CC + c0 + c4];
                Ws[c4 + 0][oo] = w.x;
                Ws[c4 + 1][oo] = w.y;
                Ws[c4 + 2][oo] = w.z;
                Ws[c4 + 3][oo] = w.w;
            }
        }
        // load X chunk: Xs[cl][nn] = X[b][c0+cl][n0+nn]
        {
            const int nn = (tid & 31) << 2;
#pragma unroll
            for (int p2 = 0; p2 < 4; p2++) {
                const int cl = (tid >> 5) + p2 * 8;
                *(float4*)&Xs[cl][nn] =
                    *(const float4*)&Xb[(size_t)(c0 + cl) * NHW + n0 + nn];
            }
        }
        __syncthreads();

#pragma unroll 8
        for (int cl = 0; cl < 32; cl++) {
            float4 w  = *(float4*)&Ws[cl][ty << 2];
            float4 x0 = *(float4*)&Xs[cl][tx << 3];
            float4 x1 = *(float4*)&Xs[cl][(tx << 3) + 4];
            float wv[4] = {w.x, w.y, w.z, w.w};
            float xv[8] = {x0.x, x0.y, x0.z, x0.w, x1.x, x1.y, x1.z, x1.w};
#pragma unroll
            for (int i = 0; i < 4; i++)
#pragma unroll
                for (int j = 0; j < 8; j++) acc[i][j] += wv[i] * xv[j];
        }
    }

    float* ob = out + (size_t)b * LL * NHW;
#pragma unroll
    for (int i = 0; i < 4; i++) {
        const int o = (ty << 2) + i;
        float4 r0 = make_float4(acc[i][0] * gain, acc[i][1] * gain,
                                acc[i][2] * gain, acc[i][3] * gain);
        float4 r1 = make_float4(acc[i][4] * gain, acc[i][5] * gain,
                                acc[i][6] * gain, acc[i][7] * gain);
        *(float4*)&ob[(size_t)o * NHW + n0 + (tx << 3)]     = r0;
        *(float4*)&ob[(size_t)o * NHW + n0 + (tx << 3) + 4] = r1;
    }
}

// ============================================================
// flash attention: Q,K,V = [b][64c][4096], no scale.
// Block: 128 queries, stream 64-key tiles, online softmax.
// Output O[b][n][c] contiguous (== the torch .view reinterpret).
// grid (32 ntiles, 8 b), 256 threads, dyn smem 102400 B.
// ============================================================
#define FLASH_SMEM 102400
__global__ __launch_bounds__(256, 2) void flash_kernel(
    const float* __restrict__ Q, const float* __restrict__ K,
    const float* __restrict__ V, float* __restrict__ O)
{
    extern __shared__ float smem[];
    float* Qs = smem;                 // [64][128]
    float* Ks = Qs + 64 * 128;        // [64][68]
    float* Vt = Ks + 64 * 68;         // [64m][68c]
    float* Ps = Vt + 64 * 68;         // [128n][68m]

    const int tid = threadIdx.x;
    const int b  = blockIdx.y;
    const int n0 = blockIdx.x * 128;
    const int ty = tid >> 4;          // n group: 8 rows each
    const int tx = tid & 15;          // m/c group: 4 each

    const float* Qb = Q + (size_t)b * LL * NHW;
    const float* Kb = K + (size_t)b * LL * NHW;
    const float* Vb = V + (size_t)b * LL * NHW;

    // load Q tile: Qs[c][nl]
    {
        const int nn = (tid & 31) << 2;
#pragma unroll
        for (int p2 = 0; p2 < 8; p2++) {
            const int c = (tid >> 5) + p2 * 8;
            *(float4*)&Qs[c * 128 + nn] =
                *(const float4*)&Qb[(size_t)c * NHW + n0 + nn];
        }
    }

    float o_acc[8][4];
    float mrun[8], lrun[8];
#pragma unroll
    for (int i = 0; i < 8; i++) {
        mrun[i] = -1e30f;
        lrun[i] = 0.f;
#pragma unroll
        for (int j = 0; j < 4; j++) o_acc[i][j] = 0.f;
    }

    for (int m0 = 0; m0 < NHW; m0 += 64) {
        __syncthreads();   // protect Ks/Vt/Ps from previous iteration readers
        // load K tile: Ks[c][ml]
        {
            const int mm = (tid & 15) << 2;
#pragma unroll
            for (int p2 = 0; p2 < 4; p2++) {
                const int c = (tid >> 4) + p2 * 16;
                *(float4*)&Ks[c * 68 + mm] =
                    *(const float4*)&Kb[(size_t)c * NHW + m0 + mm];
            }
        }
        // load V tile transposed: Vt[ml][c]
        {
            const int mg = (tid & 15) << 2;
#pragma unroll
            for (int p2 = 0; p2 < 4; p2++) {
                const int c = (tid >> 4) + p2 * 16;
                float4 v = *(const float4*)&Vb[(size_t)c * NHW + m0 + mg];
                Vt[(mg + 0) * 68 + c] = v.x;
                Vt[(mg + 1) * 68 + c] = v.y;
                Vt[(mg + 2) * 68 + c] = v.z;
                Vt[(mg + 3) * 68 + c] = v.w;
            }
        }
        __syncthreads();

        // S = Q^T K  (8n x 4m per thread)
        float s[8][4];
#pragma unroll
        for (int i = 0; i < 8; i++)
#pragma unroll
            for (int j = 0; j < 4; j++) s[i][j] = 0.f;

#pragma unroll 8
        for (int c = 0; c < 64; c++) {
            float4 q0 = *(float4*)&Qs[c * 128 + (ty << 3)];
            float4 q1 = *(float4*)&Qs[c * 128 + (ty << 3) + 4];
            float4 k  = *(float4*)&Ks[c * 68 + (tx << 2)];
            float qv[8] = {q0.x, q0.y, q0.z, q0.w, q1.x, q1.y, q1.z, q1.w};
            float kv[4] = {k.x, k.y, k.z, k.w};
#pragma unroll
            for (int i = 0; i < 8; i++)
#pragma unroll
                for (int j = 0; j < 4; j++) s[i][j] += qv[i] * kv[j];
        }

        // online softmax (rows reduce across the 16 tx lanes, width-16 xor)
#pragma unroll
        for (int i = 0; i < 8; i++) {
            float mx = fmaxf(fmaxf(s[i][0], s[i][1]), fmaxf(s[i][2], s[i][3]));
            mx = fmaxf(mx, __shfl_xor_sync(0xffffffffu, mx, 1, 16));
            mx = fmaxf(mx, __shfl_xor_sync(0xffffffffu, mx, 2, 16));
            mx = fmaxf(mx, __shfl_xor_sync(0xffffffffu, mx, 4, 16));
            mx = fmaxf(mx, __shfl_xor_sync(0xffffffffu, mx, 8, 16));
            const float mo = mrun[i];
            const float mn = fmaxf(mo, mx);
            mrun[i] = mn;
            const float esc = __expf(mo - mn);
            float rs = 0.f;
#pragma unroll
            for (int j = 0; j < 4; j++) {
                float p = __expf(s[i][j] - mn);
                s[i][j] = p;
                rs += p;
            }
            rs += __shfl_xor_sync(0xffffffffu, rs, 1, 16);
            rs += __shfl_xor_sync(0xffffffffu, rs, 2, 16);
            rs += __shfl_xor_sync(0xffffffffu, rs, 4, 16);
            rs += __shfl_xor_sync(0xffffffffu, rs, 8, 16);
            lrun[i] = lrun[i] * esc + rs;
#pragma unroll
            for (int j = 0; j < 4; j++) o_acc[i][j] *= esc;
        }

        // store P: Ps[n][m]
#pragma unroll
        for (int i = 0; i < 8; i++) {
            *(float4*)&Ps[((ty << 3) + i) * 68 + (tx << 2)] =
                make_float4(s[i][0], s[i][1], s[i][2], s[i][3]);
        }
        __syncthreads();

        // O += P V^T   (loop m by 4)
#pragma unroll 2
        for (int m = 0; m < 64; m += 4) {
            float4 v0 = *(float4*)&Vt[(m + 0) * 68 + (tx << 2)];
            float4 v1 = *(float4*)&Vt[(m + 1) * 68 + (tx << 2)];
            float4 v2 = *(float4*)&Vt[(m + 2) * 68 + (tx << 2)];
            float4 v3 = *(float4*)&Vt[(m + 3) * 68 + (tx << 2)];
#pragma unroll
            for (int i = 0; i < 8; i++) {
                float4 p = *(float4*)&Ps[((ty << 3) + i) * 68 + m];
                o_acc[i][0] += p.x * v0.x + p.y * v1.x + p.z * v2.x + p.w * v3.x;
                o_acc[i][1] += p.x * v0.y + p.y * v1.y + p.z * v2.y + p.w * v3.y;
                o_acc[i][2] += p.x * v0.z + p.y * v1.z + p.z * v2.z + p.w * v3.z;
                o_acc[i][3] += p.x * v0.w + p.y * v1.w + p.z * v2.w + p.w * v3.w;
            }
        }
    }

    float* Ob = O + (size_t)b * NHW * LL;
#pragma unroll
    for (int i = 0; i < 8; i++) {
        const float inv = 1.f / lrun[i];
        const int n = n0 + (ty << 3) + i;
        *(float4*)&Ob[(size_t)n * LL + (tx << 2)] =
            make_float4(o_acc[i][0] * inv, o_acc[i][1] * inv,
                        o_acc[i][2] * inv, o_acc[i][3] * inv);
    }
}

// ============================================================
// conv_o + residual: out[b][oc][n] = gamma*0.125*sum_l Wo[oc][l]*lat[b][l][n] + add
// grid (32 ntiles, 8 octiles, 8 b), 256 threads, dyn smem 50176 B.
// ============================================================
#define CONV_SMEM 50176
__global__ __launch_bounds__(256) void conv_o_kernel(
    const float* __restrict__ lat, const float* __restrict__ Wo,
    const float* __restrict__ addsrc, const float* __restrict__ gamma,
    float* __restrict__ out)
{
    extern __shared__ float smem[];
    float* Wos = smem;            // [l][oc_local] 64x68
    float* Ls  = Wos + 64 * 68;   // [l][n_local]  64x128

    const int tid = threadIdx.x;
    const int b   = blockIdx.z;
    const int oc0 = blockIdx.y * 64;
    const int n0  = blockIdx.x * 128;
    const int ty = tid >> 4;
    const int tx = tid & 15;

    // load Wo transposed: Wos[l][ocl]
    {
        const int l4 = (tid & 15) << 2;
#pragma unroll
        for (int p2 = 0; p2 < 4; p2++) {
            const int ocl = (tid >> 4) + p2 * 16;
            float4 w = *(const float4*)&Wo[(oc0 + ocl) * LL + l4];
            Wos[(l4 + 0) * 68 + ocl] = w.x;
            Wos[(l4 + 1) * 68 + ocl] = w.y;
            Wos[(l4 + 2) * 68 + ocl] = w.z;
            Wos[(l4 + 3) * 68 + ocl] = w.w;
        }
    }
    // load lat tile: Ls[l][nn]
    {
        const int nn = (tid & 31) << 2;
#pragma unroll
        for (int p2 = 0; p2 < 8; p2++) {
            const int l = (tid >> 5) + p2 * 8;
            *(float4*)&Ls[l * 128 + nn] =
                *(const float4*)&lat[(size_t)b * LL * NHW + (size_t)l * NHW + n0 + nn];
        }
    }
    __syncthreads();

    float acc[4][8];
#pragma unroll
    for (int i = 0; i < 4; i++)
#pragma unroll
        for (int j = 0; j < 8; j++) acc[i][j] = 0.f;

#pragma unroll 8
    for (int l = 0; l < 64; l++) {
        float4 w  = *(float4*)&Wos[l * 68 + (ty << 2)];
        float4 x0 = *(float4*)&Ls[l * 128 + (tx << 3)];
        float4 x1 = *(float4*)&Ls[l * 128 + (tx << 3) + 4];
        float wv[4] = {w.x, w.y, w.z, w.w};
        float xv[8] = {x0.x, x0.y, x0.z, x0.w, x1.x, x1.y, x1.z, x1.w};
#pragma unroll
        for (int i = 0; i < 4; i++)
#pragma unroll
            for (int j = 0; j < 8; j++) acc[i][j] += wv[i] * xv[j];
    }

    const float coeff = gamma[0] * GAIN_O;
#pragma unroll
    for (int i = 0; i < 4; i++) {
        const int oc = oc0 + (ty << 2) + i;
        const size_t base = (size_t)b * CC * NHW + (size_t)oc * NHW + n0 + (tx << 3);
        float4 a0 = *(const float4*)&addsrc[base];
        float4 a1 = *(const float4*)&addsrc[base + 4];
        float4 r0 = make_float4(coeff * acc[i][0] + a0.x, coeff * acc[i][1] + a0.y,
                                coeff * acc[i][2] + a0.z, coeff * acc[i][3] + a0.w);
        float4 r1 = make_float4(coeff * acc[i][4] + a1.x, coeff * acc[i][5] + a1.y,
                                coeff * acc[i][6] + a1.z, coeff * acc[i][7] + a1.w);
        *(float4*)&out[base]     = r0;
        *(float4*)&out[base + 4] = r1;
    }
}

// ============================================================
// MoCA attention: enc [b][64c][4096], concepts [256p][64c].
// score[n][p] = sum_c enc[c][n]*concepts[p][c]; softmax over p;
// out[n][c] = sum_p sm[n][p]*concepts[p][c].  Out [b][n][c].
// grid (64 ntiles, 8 b), 256 threads, dyn smem 223232 B.
// ============================================================
#define MOCA_SMEM 223232
__global__ __launch_bounds__(256) void moca_kernel(
    const float* __restrict__ E, const float* __restrict__ Cpt,
    float* __restrict__ O)
{
    extern __shared__ float smem[];
    float* Ct = smem;               // [64c][260p]
    float* Cs = Ct + 64 * 260;      // [256p][68c]
    float* Es = Cs + 256 * 68;      // [64c][68n]
    float* Pt = Es + 64 * 68;       // [256p][68n]

    const int tid = threadIdx.x;
    const int b  = blockIdx.y;
    const int n0 = blockIdx.x * 64;
    const int ty = tid >> 4;        // n group (4 each)
    const int tx = tid & 15;        // p group (16 each) / c group (4 each)

    // load concepts: Cs[p][c] and transposed Ct[c][p]
    {
        const int c4 = (tid & 15) << 2;
#pragma unroll
        for (int p2 = 0; p2 < 16; p2++) {
            const int p = (tid >> 4) + p2 * 16;
            float4 v = *(const float4*)&Cpt[p * 64 + c4];
            *(float4*)&Cs[p * 68 + c4] = v;
            Ct[(c4 + 0) * 260 + p] = v.x;
            Ct[(c4 + 1) * 260 + p] = v.y;
            Ct[(c4 + 2) * 260 + p] = v.z;
            Ct[(c4 + 3) * 260 + p] = v.w;
        }
    }
    // load enc tile: Es[c][nn]
    {
        const int nn = (tid & 15) << 2;
#pragma unroll
        for (int p2 = 0; p2 < 4; p2++) {
            const int c = (tid >> 4) + p2 * 16;
            *(float4*)&Es[c * 68 + nn] =
                *(const float4*)&E[(size_t)b * LL * NHW + (size_t)c * NHW + n0 + nn];
        }
    }
    __syncthreads();

    // scores: s[4n][16p]
    float s[4][16];
#pragma unroll
    for (int i = 0; i < 4; i++)
#pragma unroll
        for (int j = 0; j < 16; j++) s[i][j] = 0.f;

#pragma unroll 4
    for (int c = 0; c < 64; c++) {
        float4 q = *(float4*)&Es[c * 68 + (ty << 2)];
        float qv[4] = {q.x, q.y, q.z, q.w};
#pragma unroll
        for (int kk = 0; kk < 4; kk++) {
            float4 k = *(float4*)&Ct[c * 260 + (tx << 4) + (kk << 2)];
            float kv[4] = {k.x, k.y, k.z, k.w};
#pragma unroll
            for (int i = 0; i < 4; i++)
#pragma unroll
                for (int w = 0; w < 4; w++) s[i][(kk << 2) + w] += qv[i] * kv[w];
        }
    }

    // softmax over p (16 local x 16 tx lanes), normalize in place
#pragma unroll
    for (int i = 0; i < 4; i++) {
        float mx = -1e30f;
#pragma unroll
        for (int j = 0; j < 16; j++) mx = fmaxf(mx, s[i][j]);
        mx = fmaxf(mx, __shfl_xor_sync(0xffffffffu, mx, 1, 16));
        mx = fmaxf(mx, __shfl_xor_sync(0xffffffffu, mx, 2, 16));
        mx = fmaxf(mx, __shfl_xor_sync(0xffffffffu, mx, 4, 16));
        mx = fmaxf(mx, __shfl_xor_sync(0xffffffffu, mx, 8, 16));
        float rs = 0.f;
#pragma unroll
        for (int j = 0; j < 16; j++) {
            float p = __expf(s[i][j] - mx);
            s[i][j] = p;
            rs += p;
        }
        rs += __shfl_xor_sync(0xffffffffu, rs, 1, 16);
        rs += __shfl_xor_sync(0xffffffffu, rs, 2, 16);
        rs += __shfl_xor_sync(0xffffffffu, rs, 4, 16);
        rs += __shfl_xor_sync(0xffffffffu, rs, 8, 16);
        const float inv = 1.f / rs;
#pragma unroll
        for (int j = 0; j < 16; j++) s[i][j] *= inv;
    }

    // store Pt[p][n] (float4 over n)
#pragma unroll
    for (int pp = 0; pp < 16; pp++) {
        const int p = (tx << 4) + pp;
        *(float4*)&Pt[p * 68 + (ty << 2)] =
            make_float4(s[0][pp], s[1][pp], s[2][pp], s[3][pp]);
    }
    __syncthreads();

    // O[n][c] = sum_p Pt[p][n]*Cs[p][c]
    float o_acc[4][4];
#pragma unroll
    for (int i = 0; i < 4; i++)
#pragma unroll
        for (int j = 0; j < 4; j++) o_acc[i][j] = 0.f;

#pragma unroll 8
    for (int p = 0; p < 256; p++) {
        float4 pr = *(float4*)&Pt[p * 68 + (ty << 2)];
        float4 v  = *(float4*)&Cs[p * 68 + (tx << 2)];
        float pv[4] = {pr.x, pr.y, pr.z, pr.w};
        float vv[4] = {v.x, v.y, v.z, v.w};
#pragma unroll
        for (int i = 0; i < 4; i++)
#pragma unroll
            for (int j = 0; j < 4; j++) o_acc[i][j] += pv[i] * vv[j];
    }

#pragma unroll
    for (int i = 0; i < 4; i++) {
        const int n = n0 + (ty << 2) + i;
        *(float4*)&O[(size_t)b * NHW * LL + (size_t)n * LL + (tx << 2)] =
            make_float4(o_acc[i][0], o_acc[i][1], o_acc[i][2], o_acc[i][3]);
    }
}

// ============================================================
extern "C" void kernel_launch(void* const* d_in, const int* in_sizes, int n_in,
                              void* d_out, int out_size)
{
    (void)in_sizes; (void)n_in; (void)out_size;
    const float* fm         = (const float*)d_in[0];
    const float* concepts   = (const float*)d_in[1];
    const float* w_theta    = (const float*)d_in[2];
    const float* w_phi      = (const float*)d_in[3];
    const float* w_g        = (const float*)d_in[4];
    const float* w_o        = (const float*)d_in[5];
    const float* gamma_sa   = (const float*)d_in[6];
    const float* gamma_moca = (const float*)d_in[7];
    float* out = (float*)d_out;

    float *th, *ph, *gv, *lat, *sa, *enc, *lat2;
    cudaGetSymbolAddress((void**)&th,   g_th);
    cudaGetSymbolAddress((void**)&ph,   g_ph);
    cudaGetSymbolAddress((void**)&gv,   g_gv);
    cudaGetSymbolAddress((void**)&lat,  g_lat);
    cudaGetSymbolAddress((void**)&sa,   g_sa);
    cudaGetSymbolAddress((void**)&enc,  g_enc);
    cudaGetSymbolAddress((void**)&lat2, g_lat2);

    cudaFuncSetAttribute(flash_kernel,  cudaFuncAttributeMaxDynamicSharedMemorySize, FLASH_SMEM);
    cudaFuncSetAttribute(moca_kernel,   cudaFuncAttributeMaxDynamicSharedMemorySize, MOCA_SMEM);
    cudaFuncSetAttribute(conv_o_kernel, cudaFuncAttributeMaxDynamicSharedMemorySize, CONV_SMEM);

    const dim3 pgrid(32, 8);
    // th/ph/g projections
    proj_kernel<<<pgrid, 256>>>(fm, w_theta, th, GAIN_IN);
    proj_kernel<<<pgrid, 256>>>(fm, w_phi,   ph, GAIN_IN);
    proj_kernel<<<pgrid, 256>>>(fm, w_g,     gv, GAIN_IN);
    // self-attention
    flash_kernel<<<dim3(32, 8), 256, FLASH_SMEM>>>(th, ph, gv, lat);
    // sa_out = gamma_sa * conv_o(lat) + feature_map
    conv_o_kernel<<<dim3(32, 8, 8), 256, CONV_SMEM>>>(lat, w_o, fm, gamma_sa, sa);
    // enc projection (shared theta weights)
    proj_kernel<<<pgrid, 256>>>(sa, w_theta, enc, GAIN_IN);
    // concept attention
    moca_kernel<<<dim3(64, 8), 256, MOCA_SMEM>>>(enc, concepts, lat2);
    // out = gamma_moca * conv_o(lat2) + sa_out
    conv_o_kernel<<<dim3(32, 8, 8), 256, CONV_SMEM>>>(lat2, w_o, sa, gamma_moca, out);
}